// round 16
// baseline (speedup 1.0000x reference)
#include <cuda_runtime.h>
#include <cuda_bf16.h>
#include <cuda_fp16.h>
#include <cstdint>

// ---------------------------------------------------------------------------
// Problem constants
// ---------------------------------------------------------------------------
#define KX 8
#define BX 8192
#define DX 1024
#define HX 256
#define BM 128            // batch rows per CTA
#define NBLK (BX / BM)    // 64 row blocks

// ---------------------------------------------------------------------------
// Arch-feature gate (tcgen05 only in the sm_103a-specific pass)
// ---------------------------------------------------------------------------
#if defined(__CUDA_ARCH__) && (__CUDA_ARCH__ >= 1000) && \
    (defined(__CUDA_ARCH_FEAT_SM103_ALL) || defined(__CUDA_ARCH_FEAT_SM100_ALL) || \
     defined(__CUDA_ARCH_SPECIFIC__) || defined(__CUDA_ARCH_FAMILY_SPECIFIC__))
#define AE_TC 1
#else
#define AE_TC 0
#endif

// ---------------------------------------------------------------------------
// Device scratch (fp16 2-level splits)
// ---------------------------------------------------------------------------
__device__ float g_recon[(size_t)KX * BX * DX];                 // 256 MB
__device__ float g_err[KX * BX];
__device__ int   g_done[NBLK];
__device__ __half g_xs [(size_t)2 * BX * DX];                   // 32 MB
__device__ __half g_w1t[(size_t)2 * KX * HX * DX];              // 8.4 MB
__device__ __half g_w2t[(size_t)2 * KX * DX * HX];              // 8.4 MB

// ---------------------------------------------------------------------------
// Helpers
// ---------------------------------------------------------------------------
__device__ __forceinline__ uint32_t smem_u32(const void* p) {
    uint32_t a;
    asm("{ .reg .u64 t; cvta.to.shared.u64 t, %1; cvt.u32.u64 %0, t; }" : "=r"(a) : "l"(p));
    return a;
}

#define SW128(off) ((off) ^ (((off) >> 3) & 0x70))

#define CP16(dst, src) \
    asm volatile("cp.async.cg.shared.global [%0], [%1], 16;" :: "r"(dst), "l"(src))
// .noinc consumes one of the barrier's init-count arrivals on completion.
#define CP_ASYNC_ARRIVE(mb) \
    asm volatile("cp.async.mbarrier.arrive.noinc.shared::cta.b64 [%0];" :: "r"((uint32_t)(mb)) : "memory")

#define MBARRIER_INIT(a, c) \
    asm volatile("mbarrier.init.shared.b64 [%0], %1;" :: "r"((uint32_t)(a)), "r"((uint32_t)(c)) : "memory")
#define MBARRIER_INVAL(a) \
    asm volatile("mbarrier.inval.shared.b64 [%0];" :: "r"((uint32_t)(a)) : "memory")
#define MBARRIER_ARRIVE(a) \
    asm volatile("mbarrier.arrive.shared.b64 _, [%0];" :: "r"((uint32_t)(a)) : "memory")

#define MBARRIER_WAIT_PARITY(mbar_smem_addr, phase_parity) do { \
    uint32_t _mbar = (uint32_t)(mbar_smem_addr); \
    uint32_t _parity = (uint32_t)(phase_parity); \
    uint32_t _done; \
    asm volatile( \
        "{\n\t.reg .pred p;\n\t" \
        "mbarrier.try_wait.parity.acquire.cta.shared::cta.b64 p, [%1], %2;\n\t" \
        "selp.b32 %0, 1, 0, p;\n\t}" \
        : "=r"(_done) : "r"(_mbar), "r"(_parity) : "memory"); \
    if (!_done) { \
        asm volatile( \
            "{\n\t.reg .pred P1;\n\t" \
            "WAIT_LOOP_%=:\n\t" \
            "mbarrier.try_wait.parity.acquire.cta.shared::cta.b64 P1, [%0], %1, 0x989680;\n\t" \
            "@P1 bra.uni WAIT_DONE_%=;\n\t" \
            "bra.uni WAIT_LOOP_%=;\n\t" \
            "WAIT_DONE_%=:\n\t}" \
            :: "r"(_mbar), "r"(_parity) : "memory"); \
    } \
} while (0)

// fp16 Dekker 2-split (residual exact in fp32)
__device__ __forceinline__ void split2(float v, __half& h0, __half& h1) {
    h0 = __float2half_rn(v);
    h1 = __float2half_rn(v - __half2float(h0));
}
__device__ __forceinline__ uint32_t pack2h(__half lo, __half hi) {
    return (uint32_t)__half_as_ushort(lo) | ((uint32_t)__half_as_ushort(hi) << 16);
}

// ---------------------------------------------------------------------------
// tcgen05 helpers
// ---------------------------------------------------------------------------
#if AE_TC
#define TCGEN05_ALLOC(sa, n) \
    asm volatile("tcgen05.alloc.cta_group::1.sync.aligned.shared::cta.b32 [%0], %1;" \
                 :: "r"((uint32_t)(sa)), "r"((uint32_t)(n)) : "memory")
#define TCGEN05_DEALLOC(t, n) \
    asm volatile("tcgen05.dealloc.cta_group::1.sync.aligned.b32 %0, %1;" :: "r"(t), "r"((uint32_t)(n)))
#define TCGEN05_RELINQ() \
    asm volatile("tcgen05.relinquish_alloc_permit.cta_group::1.sync.aligned;")
#define TCGEN05_COMMIT(mb) \
    asm volatile("tcgen05.commit.cta_group::1.mbarrier::arrive::one.shared::cluster.b64 [%0];" \
                 :: "r"((uint32_t)(mb)) : "memory")
#define TCGEN05_WAIT_LD() asm volatile("tcgen05.wait::ld.sync.aligned;" ::: "memory")
#define TCGEN05_WAIT_ST() asm volatile("tcgen05.wait::st.sync.aligned;" ::: "memory")
#define TCGEN05_FENCE_BEFORE() asm volatile("tcgen05.fence::before_thread_sync;" ::: "memory")
#define TCGEN05_FENCE_AFTER()  asm volatile("tcgen05.fence::after_thread_sync;" ::: "memory")
#define FENCE_PROXY_ASYNC() asm volatile("fence.proxy.async.shared::cta;" ::: "memory")

#define LDTM32(r, ta) \
    asm volatile( \
        "tcgen05.ld.sync.aligned.32x32b.x32.b32 " \
        "{%0, %1, %2, %3, %4, %5, %6, %7, " \
        " %8, %9, %10, %11, %12, %13, %14, %15, " \
        " %16, %17, %18, %19, %20, %21, %22, %23, " \
        " %24, %25, %26, %27, %28, %29, %30, %31}, [%32];" \
        : "=r"((r)[0]),  "=r"((r)[1]),  "=r"((r)[2]),  "=r"((r)[3]), \
          "=r"((r)[4]),  "=r"((r)[5]),  "=r"((r)[6]),  "=r"((r)[7]), \
          "=r"((r)[8]),  "=r"((r)[9]),  "=r"((r)[10]), "=r"((r)[11]), \
          "=r"((r)[12]), "=r"((r)[13]), "=r"((r)[14]), "=r"((r)[15]), \
          "=r"((r)[16]), "=r"((r)[17]), "=r"((r)[18]), "=r"((r)[19]), \
          "=r"((r)[20]), "=r"((r)[21]), "=r"((r)[22]), "=r"((r)[23]), \
          "=r"((r)[24]), "=r"((r)[25]), "=r"((r)[26]), "=r"((r)[27]), \
          "=r"((r)[28]), "=r"((r)[29]), "=r"((r)[30]), "=r"((r)[31]) \
        : "r"(ta))

#define STTM16(ta, r) \
    asm volatile( \
        "tcgen05.st.sync.aligned.32x32b.x16.b32 [%0], " \
        "{%1, %2, %3, %4, %5, %6, %7, %8, " \
        " %9, %10, %11, %12, %13, %14, %15, %16};" \
        :: "r"(ta), \
           "r"((r)[0]),  "r"((r)[1]),  "r"((r)[2]),  "r"((r)[3]), \
           "r"((r)[4]),  "r"((r)[5]),  "r"((r)[6]),  "r"((r)[7]), \
           "r"((r)[8]),  "r"((r)[9]),  "r"((r)[10]), "r"((r)[11]), \
           "r"((r)[12]), "r"((r)[13]), "r"((r)[14]), "r"((r)[15]) \
        : "memory")

static constexpr uint64_t DESC_BASE_SW128 =
    (uint64_t(2) << 61) | (uint64_t(1) << 46) | (uint64_t(64) << 32) | (uint64_t(1) << 16);
#define MAKE_DESC(addr) (DESC_BASE_SW128 | ((uint64_t)((addr) >> 4) & 0x3FFF))

__device__ __forceinline__ void mma_f16_ss(uint32_t d, uint64_t ad, uint64_t bd,
                                           uint32_t idesc, bool en) {
    uint32_t e = en ? 1u : 0u;
    asm volatile(
        "{\n\t.reg .pred p;\n\tsetp.ne.u32 p, %4, 0;\n\t"
        "tcgen05.mma.cta_group::1.kind::f16 [%0], %1, %2, %3, {%5, %5, %5, %5}, p;\n\t}"
        :: "r"(d), "l"(ad), "l"(bd), "r"(idesc), "r"(e), "r"(0u) : "memory");
}
__device__ __forceinline__ void mma_f16_ts(uint32_t d, uint32_t at, uint64_t bd,
                                           uint32_t idesc, bool en) {
    uint32_t e = en ? 1u : 0u;
    asm volatile(
        "{\n\t.reg .pred p;\n\tsetp.ne.u32 p, %4, 0;\n\t"
        "tcgen05.mma.cta_group::1.kind::f16 [%0], [%1], %2, %3, {%5, %5, %5, %5}, p;\n\t}"
        :: "r"(d), "r"(at), "l"(bd), "r"(idesc), "r"(e), "r"(0u) : "memory");
}
#endif  // AE_TC

// ---------------------------------------------------------------------------
// SMEM layout (bytes)
// ---------------------------------------------------------------------------
#define SM_S1A     0           // stage1 A bufs: 2 x 32KB (2 levels x 16KB)
#define SM_S1B     65536       // stage1 B bufs: 2 x 64KB (2 levels x 32KB, 256 rows)
#define SM_S2B     65536       // stage2 B bufs: 4 x 32KB (overlays S1B region)
#define SM_B1S     196608      // b1 copy (1 KB)
#define SM_B2S     197632      // b2 copy (4 KB)
#define SM_FULL(i) (201728 + (i) * 8)   // 4 full bars (producer -> issuer)
#define SM_SD1(i)  (201760 + (i) * 8)   // 2 stage-1 slot-done bars
#define SM_SD2(i)  (201776 + (i) * 8)   // 8 stage-2 slot-done bars
#define SM_ED(i)   (201840 + (i) * 8)   // 2 epilogue-done bars
#define SM_TMEMPTR 201856
#define SM_LASTF   201864      // last-CTA flag for fused gather
#define SMEM_TOTAL 201984

// TMEM column layout (512 cols)
#define TM_D1   0      // stage1 accum h [128 x 256] f32 (dead after epi1)
#define TM_D2   0      // stage2 ping-pong accum [128 x 64] f32 x 2 — in dead D1
#define TM_A0   256    // h split level0 (fp16x2, 128 cols)
#define TM_A1   384    // h split level1

// idesc: dtype F32 (bit4) | atype/btype F16=0 | N/8<<17 | M/16<<24
#define IDESC_N256 ((8u << 24) | (32u << 17) | (1u << 4))
#define IDESC_N64  ((8u << 24) | (8u  << 17) | (1u << 4))

// ---------------------------------------------------------------------------
// Fused prep kernel: split_x + tr_w1 + tr_w2 + g_done reset, one launch.
// ---------------------------------------------------------------------------
#define PREP_SPLITX_BLOCKS (BX * DX / 2 / 256)              // 16384
#define PREP_W1_BLOCKS     ((HX / 32) * (DX / 32) * KX)     // 2048
#define PREP_W2_BLOCKS     ((DX / 32) * (HX / 32) * KX)     // 2048
#define PREP_TOTAL_BLOCKS  (PREP_SPLITX_BLOCKS + PREP_W1_BLOCKS + PREP_W2_BLOCKS)

__global__ __launch_bounds__(256)
void prep_kernel(const float* __restrict__ x,
                 const float* __restrict__ W1,
                 const float* __restrict__ W2)
{
    __shared__ float t[32][33];
    const int blk = blockIdx.x;
    const int tid = threadIdx.x;

    if (blk == 0 && tid < NBLK) g_done[tid] = 0;   // reset completion counters

    if (blk < PREP_SPLITX_BLOCKS) {
        // ---- split_x ----
        size_t i2 = (size_t)blk * 256 + tid;
        float2 v = ((const float2*)x)[i2];
        __half a0, a1, b0, b1;
        split2(v.x, a0, a1);
        split2(v.y, b0, b1);
        const size_t N = (size_t)BX * DX;
        ((uint32_t*)g_xs)[i2]         = pack2h(a0, b0);
        ((uint32_t*)g_xs)[N / 2 + i2] = pack2h(a1, b1);
        return;
    }

    const int tx = tid & 31, ty = tid >> 5;     // (32, 8) thread shape

    if (blk < PREP_SPLITX_BLOCKS + PREP_W1_BLOCKS) {
        // ---- tr_w1: idx -> (h0, d0, k) ----
        int idx = blk - PREP_SPLITX_BLOCKS;
        int h0 = (idx % (HX / 32)) * 32;
        int d0 = ((idx / (HX / 32)) % (DX / 32)) * 32;
        int k  = idx / ((HX / 32) * (DX / 32));
        #pragma unroll
        for (int r = 0; r < 4; r++) {
            int d = d0 + ty + r * 8;
            t[ty + r * 8][tx] = W1[((size_t)k * DX + d) * HX + h0 + tx];
        }
        __syncthreads();
        const size_t LVL = (size_t)KX * HX * DX;
        #pragma unroll
        for (int r = 0; r < 4; r++) {
            int h = h0 + ty + r * 8;
            float v = t[tx][ty + r * 8];
            __half a0, a1;
            split2(v, a0, a1);
            size_t base = ((size_t)k * HX + h) * DX + d0 + tx;
            g_w1t[base] = a0; g_w1t[LVL + base] = a1;
        }
        return;
    }

    {
        // ---- tr_w2: idx -> (d0, h0, k) ----
        int idx = blk - PREP_SPLITX_BLOCKS - PREP_W1_BLOCKS;
        int d0 = (idx % (DX / 32)) * 32;
        int h0 = ((idx / (DX / 32)) % (HX / 32)) * 32;
        int k  = idx / ((DX / 32) * (HX / 32));
        #pragma unroll
        for (int r = 0; r < 4; r++) {
            int h = h0 + ty + r * 8;
            t[ty + r * 8][tx] = W2[((size_t)k * HX + h) * DX + d0 + tx];
        }
        __syncthreads();
        const size_t LVL = (size_t)KX * DX * HX;
        #pragma unroll
        for (int r = 0; r < 4; r++) {
            int d = d0 + ty + r * 8;
            float v = t[tx][ty + r * 8];
            __half a0, a1;
            split2(v, a0, a1);
            size_t base = ((size_t)k * DX + d) * HX + h0 + tx;
            g_w2t[base] = a0; g_w2t[LVL + base] = a1;
        }
    }
}

// ---------------------------------------------------------------------------
// Last-CTA gather (shared by both compile paths). Crew = 128 threads
// (wid 0-3). Warp-per-row over 128 rows; .cg loads bypass L1 (cross-CTA data).
// ---------------------------------------------------------------------------
__device__ __forceinline__ void gather_block(float* __restrict__ out, int b0,
                                             int wid, int lane) {
    for (int rr = wid; rr < BM; rr += 4) {
        int gb = b0 + rr;
        float best = __ldcg(&g_err[gb]);
        int bi = 0;
        #pragma unroll
        for (int kk = 1; kk < KX; kk++) {
            float e = __ldcg(&g_err[(size_t)kk * BX + gb]);
            if (e < best) { best = e; bi = kk; }
        }
        const float4* src = (const float4*)(g_recon + ((size_t)bi * BX + gb) * DX);
        float4* dst = (float4*)(out + (size_t)gb * DX);
        #pragma unroll
        for (int j = 0; j < 8; j++)
            dst[lane + 32 * j] = __ldcg(src + lane + 32 * j);
    }
}

// ---------------------------------------------------------------------------
// Main fused kernel: warp-specialized, 48 slots (R11/R15 protocol) +
// last-CTA argmin/gather fused into the epilogue tail.
// ---------------------------------------------------------------------------
__global__ __launch_bounds__(256, 1)
void ae_main(const float* __restrict__ x,
             const float* __restrict__ b1,
             const float* __restrict__ b2,
             float* __restrict__ out)
{
#if AE_TC
    extern __shared__ char smem[];
    const uint32_t sb = smem_u32(smem);
    const int tid = threadIdx.x, wid = tid >> 5, lane = tid & 31;
    const int k = blockIdx.y, b0 = blockIdx.x * BM;

    if (wid == 0) TCGEN05_ALLOC(sb + SM_TMEMPTR, 512);
    if (tid == 0) {
        #pragma unroll
        for (int i = 0; i < 4; i++) MBARRIER_INIT(SM_FULL(i) + sb, 96);
        #pragma unroll
        for (int i = 0; i < 2; i++) MBARRIER_INIT(SM_SD1(i) + sb, 1);
        #pragma unroll
        for (int i = 0; i < 8; i++) MBARRIER_INIT(SM_SD2(i) + sb, 1);
        #pragma unroll
        for (int i = 0; i < 2; i++) MBARRIER_INIT(SM_ED(i) + sb, 128);
    }
    if (tid < 64) {
        float4 v = ((const float4*)(b1 + (size_t)k * HX))[tid];
        ((float4*)(smem + SM_B1S))[tid] = v;
    }
    {
        float4 v = ((const float4*)(b2 + (size_t)k * DX))[tid];
        ((float4*)(smem + SM_B2S))[tid] = v;
    }
    __syncthreads();
    uint32_t tb;
    asm volatile("ld.shared.b32 %0, [%1];" : "=r"(tb) : "r"(sb + SM_TMEMPTR));

    // 3 cross-products of the 2-level splits: (A0,B0), (A1,B0), (A0,B1)
    const int pa[3] = {0, 1, 0};
    const int pb[3] = {0, 0, 1};

    if (tid >= 128 && tid < 224) {
        // ===================== PRODUCERS (warps 4-6) ========================
        const int ptid = tid - 128;
        // stage 1: 16 slots (s == kc), A and B double-buffered on s&1.
        for (int s = 0; s < 16; s++) {
            if (s >= 2)
                MBARRIER_WAIT_PARITY(sb + SM_SD1(s & 1), ((s - 2) >> 1) & 1);
            {   // A tile: 2 levels x [128 rows x 64] fp16
                uint32_t base = sb + SM_S1A + (s & 1) * 32768;
                for (int t = ptid; t < 2048; t += 96) {
                    int l = t >> 10, rem = t & 1023, r = rem >> 3, c = rem & 7;
                    uint32_t dst = base + l * 16384 + SW128((uint32_t)(r * 128 + c * 16));
                    const __half* src = g_xs + ((size_t)l * BX + b0 + r) * DX + s * 64 + c * 8;
                    CP16(dst, src);
                }
            }
            {   // B tile: 2 levels x [256 h-rows x 64] fp16
                uint32_t base = sb + SM_S1B + (s & 1) * 65536;
                for (int t = ptid; t < 4096; t += 96) {
                    int l = t >> 11, rem = t & 2047, r = rem >> 3, c = rem & 7;
                    uint32_t dst = base + l * 32768 + SW128((uint32_t)(r * 128 + c * 16));
                    const __half* src =
                        g_w1t + (((size_t)l * KX + k) * HX + r) * DX + s * 64 + c * 8;
                    CP16(dst, src);
                }
            }
            CP_ASYNC_ARRIVE(sb + SM_FULL(s & 3));
        }
        // stage 2: 32 slots (t = 2*nc + kh), bufs t&3 (32KB over the S1B region).
        for (int t = 0; t < 32; t++) {
            if (t < 2)       MBARRIER_WAIT_PARITY(sb + SM_SD1(0), 1);
            else if (t < 4)  MBARRIER_WAIT_PARITY(sb + SM_SD1(1), 1);
            else             MBARRIER_WAIT_PARITY(sb + SM_SD2((t - 4) & 7), ((t - 4) >> 3) & 1);
            {   // 2 levels x 2 ks-sub (K=64) x [64 d-rows x 64] = 32 KB
                const int nc = t >> 1, kh = t & 1;
                uint32_t base = sb + SM_S2B + (t & 3) * 32768;
                for (int u = ptid; u < 2048; u += 96) {
                    int l = u >> 10, rem = u & 1023, ks = rem >> 9, rem2 = rem & 511;
                    int r = rem2 >> 3, c = rem2 & 7;
                    uint32_t dst = base + l * 16384 + ks * 8192 + SW128((uint32_t)(r * 128 + c * 16));
                    const __half* src =
                        g_w2t + (((size_t)l * KX + k) * DX + nc * 64 + r) * HX + kh * 128 + ks * 64 + c * 8;
                    CP16(dst, src);
                }
            }
            CP_ASYNC_ARRIVE(sb + SM_FULL(t & 3));
        }
    } else if (tid == 224) {
        // ===================== MMA ISSUER (warp 7, lane 0) ==================
        // stage 1: 16 slots, N=256 atoms, 12 dispatches/slot
        for (int s = 0; s < 16; s++) {
            MBARRIER_WAIT_PARITY(sb + SM_FULL(s & 3), (s >> 2) & 1);
            FENCE_PROXY_ASYNC();
            uint32_t abuf = sb + SM_S1A + (s & 1) * 32768;
            uint32_t bbuf = sb + SM_S1B + (s & 1) * 65536;
            #pragma unroll
            for (int p = 0; p < 3; p++) {
                uint64_t ad = MAKE_DESC(abuf + pa[p] * 16384);
                uint64_t bd = MAKE_DESC(bbuf + pb[p] * 32768);
                #pragma unroll
                for (int st = 0; st < 4; st++) {
                    bool en = !(s == 0 && p == 0 && st == 0);
                    mma_f16_ss(tb + TM_D1, ad + st * 2, bd + st * 2, IDESC_N256, en);
                }
            }
            TCGEN05_COMMIT(sb + SM_SD1(s & 1));
        }
        // stage 2: 32 slots, 24 dispatches/slot
        MBARRIER_WAIT_PARITY(sb + SM_ED(0), 0);          // epilogue-1 done (A in TMEM)
        TCGEN05_FENCE_AFTER();
        const uint32_t abase[2] = {TM_A0, TM_A1};
        for (int t = 0; t < 32; t++) {
            const int nc = t >> 1, kh = t & 1;
            if (kh == 0 && nc >= 2) {                    // D2 ping-pong guard
                if (nc & 1) MBARRIER_WAIT_PARITY(sb + SM_ED(1), ((nc - 3) >> 1) & 1);
                else        MBARRIER_WAIT_PARITY(sb + SM_ED(0), (nc >> 1) & 1);
                TCGEN05_FENCE_AFTER();
            }
            MBARRIER_WAIT_PARITY(sb + SM_FULL(t & 3), (t >> 2) & 1);
            FENCE_PROXY_ASYNC();
            uint32_t bbuf = sb + SM_S2B + (t & 3) * 32768;
            uint32_t d = tb + TM_D2 + (nc & 1) * 64;
            #pragma unroll
            for (int ks = 0; ks < 2; ks++) {
                #pragma unroll
                for (int p = 0; p < 3; p++) {
                    uint64_t bd = MAKE_DESC(bbuf + pb[p] * 16384 + ks * 8192);
                    #pragma unroll
                    for (int st = 0; st < 4; st++) {
                        bool en = !(kh == 0 && ks == 0 && p == 0 && st == 0);
                        uint32_t at = tb + abase[pa[p]] + (kh * 8 + ks * 4 + st) * 8;
                        mma_f16_ts(d, at, bd + st * 2, IDESC_N64, en);
                    }
                }
            }
            TCGEN05_COMMIT(sb + SM_SD2(t & 7));
        }
    } else if (tid < 128) {
        // ===================== EPILOGUE CREW (warps 0-3) ====================
        for (int u = 0; u < 8; u++)
            MBARRIER_WAIT_PARITY(sb + SM_SD1(1), u & 1);
        TCGEN05_FENCE_AFTER();

        // epilogue 1: bias+relu, split h -> fp16x2 into TMEM.
        {
            const uint32_t woff = (uint32_t)wid << 21;
            const float* b1s = (const float*)(smem + SM_B1S);
            for (int c0 = 0; c0 < 256; c0 += 32) {
                uint32_t r[32];
                LDTM32(r, tb + TM_D1 + c0);
                TCGEN05_WAIT_LD();
                uint32_t p0[16], p1[16];
                #pragma unroll
                for (int t2 = 0; t2 < 16; t2++) {
                    float v0 = __uint_as_float(r[2 * t2])     + b1s[c0 + 2 * t2];
                    float v1 = __uint_as_float(r[2 * t2 + 1]) + b1s[c0 + 2 * t2 + 1];
                    v0 = fmaxf(v0, 0.0f); v1 = fmaxf(v1, 0.0f);
                    __half a0, a1, c0h, c1h;
                    split2(v0, a0, a1);
                    split2(v1, c0h, c1h);
                    p0[t2] = pack2h(a0, c0h);
                    p1[t2] = pack2h(a1, c1h);
                }
                STTM16(tb + TM_A0 + (c0 >> 1) + woff, p0);
                STTM16(tb + TM_A1 + (c0 >> 1) + woff, p1);
                TCGEN05_WAIT_ST();
            }
            TCGEN05_FENCE_BEFORE();
        }
        MBARRIER_ARRIVE(sb + SM_ED(0));   // ED(0) completion #1

        // epilogue 2: per-nc bias + err + recon store.
        float errsum = 0.0f;
        const float* b2s = (const float*)(smem + SM_B2S);
        const int row = wid * 32 + lane, gr = b0 + row;
        for (int nc = 0; nc < 16; nc++) {
            MBARRIER_WAIT_PARITY(sb + SM_SD2((2 * nc + 1) & 7), ((2 * nc + 1) >> 3) & 1);
            TCGEN05_FENCE_AFTER();
            uint32_t r0[32], r1[32];
            LDTM32(r0, tb + TM_D2 + (nc & 1) * 64);
            LDTM32(r1, tb + TM_D2 + (nc & 1) * 64 + 32);
            TCGEN05_WAIT_LD();
            const float* xr = x + (size_t)gr * DX + nc * 64;
            float* rr = g_recon + ((size_t)k * BX + gr) * DX + nc * 64;
            #pragma unroll
            for (int q = 0; q < 16; q++) {
                int c = q * 4;
                const uint32_t* rv = (c < 32) ? (r0 + c) : (r1 + c - 32);
                float4 xv = *(const float4*)(xr + c);
                float4 ov;
                ov.x = __uint_as_float(rv[0]) + b2s[nc * 64 + c + 0];
                ov.y = __uint_as_float(rv[1]) + b2s[nc * 64 + c + 1];
                ov.z = __uint_as_float(rv[2]) + b2s[nc * 64 + c + 2];
                ov.w = __uint_as_float(rv[3]) + b2s[nc * 64 + c + 3];
                *(float4*)(rr + c) = ov;
                float d0 = ov.x - xv.x, d1 = ov.y - xv.y;
                float d2 = ov.z - xv.z, d3 = ov.w - xv.w;
                errsum = fmaf(d0, d0, errsum);
                errsum = fmaf(d1, d1, errsum);
                errsum = fmaf(d2, d2, errsum);
                errsum = fmaf(d3, d3, errsum);
            }
            TCGEN05_FENCE_BEFORE();
            MBARRIER_ARRIVE(sb + SM_ED(nc & 1));
        }
        g_err[(size_t)k * BX + b0 + row] = errsum * (1.0f / DX);

        // ---------- fused argmin + gather (last CTA of this row block) ------
        __threadfence();                                   // publish recon + err
        asm volatile("bar.sync 1, 128;" ::: "memory");     // crew-wide
        if (tid == 0) {
            int prev = atomicAdd(&g_done[blockIdx.x], 1);
            ((volatile int*)(smem + SM_LASTF))[0] = (prev == KX - 1) ? 1 : 0;
        }
        asm volatile("bar.sync 1, 128;" ::: "memory");
        if (((volatile int*)(smem + SM_LASTF))[0]) {
            __threadfence();                               // order after observation
            gather_block(out, b0, wid, lane);
        }
    }
    // (tid 225..255: idle straight to the final barrier)

    __syncthreads();
    if (tid == 0) {
        #pragma unroll
        for (int i = 0; i < 4; i++) MBARRIER_INVAL(SM_FULL(i) + sb);
        #pragma unroll
        for (int i = 0; i < 2; i++) MBARRIER_INVAL(SM_SD1(i) + sb);
        #pragma unroll
        for (int i = 0; i < 8; i++) MBARRIER_INVAL(SM_SD2(i) + sb);
        #pragma unroll
        for (int i = 0; i < 2; i++) MBARRIER_INVAL(SM_ED(i) + sb);
    }
    __syncthreads();
    if (wid == 0) {
        TCGEN05_RELINQ();
        TCGEN05_DEALLOC(tb, 512);
    }
#else
    // ---------------- Correct scalar fallback (non-arch-specific pass) -------
    extern __shared__ char smem[];
    float* h_f = (float*)smem;                     // [128][256]
    float* errsh = h_f + BM * HX;                  // [128]
    int*   lastf = (int*)(errsh + BM);
    const int tid = threadIdx.x, wid = tid >> 5, lane = tid & 31;
    const int k = blockIdx.y, b0 = blockIdx.x * BM;
    const size_t L1 = (size_t)KX * HX * DX;
    const size_t L2 = (size_t)KX * DX * HX;

    for (int i = tid; i < BM * HX; i += 256) {
        int r = i >> 8, c = i & 255;
        float s = b1[(size_t)k * HX + c];
        const float* xr = x + (size_t)(b0 + r) * DX;
        size_t wb = ((size_t)k * HX + c) * DX;
        for (int d = 0; d < DX; d++) {
            float w = __half2float(g_w1t[wb + d]) + __half2float(g_w1t[L1 + wb + d]);
            s = fmaf(xr[d], w, s);
        }
        h_f[i] = fmaxf(s, 0.0f);
    }
    __syncthreads();
    if (tid < 128) errsh[tid] = 0.0f;
    __syncthreads();
    for (int i = tid; i < BM * DX; i += 256) {
        int r = i >> 10, c = i & 1023;
        float s = b2[(size_t)k * DX + c];
        size_t wb = ((size_t)k * DX + c) * HX;
        for (int hh = 0; hh < HX; hh++) {
            float w = __half2float(g_w2t[wb + hh]) + __half2float(g_w2t[L2 + wb + hh]);
            s = fmaf(h_f[r * HX + hh], w, s);
        }
        g_recon[((size_t)k * BX + b0 + r) * DX + c] = s;
        float d = s - x[(size_t)(b0 + r) * DX + c];
        atomicAdd(&errsh[r], d * d);
    }
    __syncthreads();
    if (tid < 128) g_err[(size_t)k * BX + b0 + tid] = errsh[tid] * (1.0f / DX);
    __threadfence();
    __syncthreads();
    if (tid == 0) {
        int prev = atomicAdd(&g_done[blockIdx.x], 1);
        *lastf = (prev == KX - 1) ? 1 : 0;
    }
    __syncthreads();
    if (*lastf && tid < 128) {
        __threadfence();
        gather_block(out, b0, wid, lane);
    }
#endif
}

// ---------------------------------------------------------------------------
// Host launcher
// ---------------------------------------------------------------------------
extern "C" void kernel_launch(void* const* d_in, const int* in_sizes, int n_in,
                              void* d_out, int out_size)
{
    const float* x  = (const float*)d_in[0];
    const float* W1 = (const float*)d_in[1];
    const float* b1 = (const float*)d_in[2];
    const float* W2 = (const float*)d_in[3];
    const float* b2 = (const float*)d_in[4];
    float* out = (float*)d_out;

    prep_kernel<<<PREP_TOTAL_BLOCKS, 256>>>(x, W1, W2);

    cudaFuncSetAttribute(ae_main, cudaFuncAttributeMaxDynamicSharedMemorySize, SMEM_TOTAL);
    ae_main<<<dim3(BX / BM, KX), 256, SMEM_TOTAL>>>(x, b1, b2, out);
}

// round 17
// speedup vs baseline: 1.3852x; 1.3852x over previous
#include <cuda_runtime.h>
#include <cuda_bf16.h>
#include <cuda_fp16.h>
#include <cstdint>

// ---------------------------------------------------------------------------
// Problem constants
// ---------------------------------------------------------------------------
#define KX 8
#define BX 8192
#define DX 1024
#define HX 256
#define BM 128            // batch rows per CTA

// ---------------------------------------------------------------------------
// Arch-feature gate (tcgen05 only in the sm_103a-specific pass)
// ---------------------------------------------------------------------------
#if defined(__CUDA_ARCH__) && (__CUDA_ARCH__ >= 1000) && \
    (defined(__CUDA_ARCH_FEAT_SM103_ALL) || defined(__CUDA_ARCH_FEAT_SM100_ALL) || \
     defined(__CUDA_ARCH_SPECIFIC__) || defined(__CUDA_ARCH_FAMILY_SPECIFIC__))
#define AE_TC 1
#else
#define AE_TC 0
#endif

// ---------------------------------------------------------------------------
// Device scratch (fp16 2-level splits)
// ---------------------------------------------------------------------------
__device__ float g_recon[(size_t)KX * BX * DX];                 // 256 MB
__device__ float g_err[KX * BX];
__device__ __half g_xs [(size_t)2 * BX * DX];                   // 32 MB
__device__ __half g_w1t[(size_t)2 * KX * HX * DX];              // 8.4 MB
__device__ __half g_w2t[(size_t)2 * KX * DX * HX];              // 8.4 MB

// ---------------------------------------------------------------------------
// Helpers
// ---------------------------------------------------------------------------
__device__ __forceinline__ uint32_t smem_u32(const void* p) {
    uint32_t a;
    asm("{ .reg .u64 t; cvta.to.shared.u64 t, %1; cvt.u32.u64 %0, t; }" : "=r"(a) : "l"(p));
    return a;
}

#define SW128(off) ((off) ^ (((off) >> 3) & 0x70))

#define CP16(dst, src) \
    asm volatile("cp.async.cg.shared.global [%0], [%1], 16;" :: "r"(dst), "l"(src))
// .noinc consumes one of the barrier's init-count arrivals on completion.
#define CP_ASYNC_ARRIVE(mb) \
    asm volatile("cp.async.mbarrier.arrive.noinc.shared::cta.b64 [%0];" :: "r"((uint32_t)(mb)) : "memory")

#define MBARRIER_INIT(a, c) \
    asm volatile("mbarrier.init.shared.b64 [%0], %1;" :: "r"((uint32_t)(a)), "r"((uint32_t)(c)) : "memory")
#define MBARRIER_INVAL(a) \
    asm volatile("mbarrier.inval.shared.b64 [%0];" :: "r"((uint32_t)(a)) : "memory")
#define MBARRIER_ARRIVE(a) \
    asm volatile("mbarrier.arrive.shared.b64 _, [%0];" :: "r"((uint32_t)(a)) : "memory")

#define MBARRIER_WAIT_PARITY(mbar_smem_addr, phase_parity) do { \
    uint32_t _mbar = (uint32_t)(mbar_smem_addr); \
    uint32_t _parity = (uint32_t)(phase_parity); \
    uint32_t _done; \
    asm volatile( \
        "{\n\t.reg .pred p;\n\t" \
        "mbarrier.try_wait.parity.acquire.cta.shared::cta.b64 p, [%1], %2;\n\t" \
        "selp.b32 %0, 1, 0, p;\n\t}" \
        : "=r"(_done) : "r"(_mbar), "r"(_parity) : "memory"); \
    if (!_done) { \
        asm volatile( \
            "{\n\t.reg .pred P1;\n\t" \
            "WAIT_LOOP_%=:\n\t" \
            "mbarrier.try_wait.parity.acquire.cta.shared::cta.b64 P1, [%0], %1, 0x989680;\n\t" \
            "@P1 bra.uni WAIT_DONE_%=;\n\t" \
            "bra.uni WAIT_LOOP_%=;\n\t" \
            "WAIT_DONE_%=:\n\t}" \
            :: "r"(_mbar), "r"(_parity) : "memory"); \
    } \
} while (0)

// fp16 Dekker 2-split (residual exact in fp32)
__device__ __forceinline__ void split2(float v, __half& h0, __half& h1) {
    h0 = __float2half_rn(v);
    h1 = __float2half_rn(v - __half2float(h0));
}
__device__ __forceinline__ uint32_t pack2h(__half lo, __half hi) {
    return (uint32_t)__half_as_ushort(lo) | ((uint32_t)__half_as_ushort(hi) << 16);
}

// ---------------------------------------------------------------------------
// tcgen05 helpers
// ---------------------------------------------------------------------------
#if AE_TC
#define TCGEN05_ALLOC(sa, n) \
    asm volatile("tcgen05.alloc.cta_group::1.sync.aligned.shared::cta.b32 [%0], %1;" \
                 :: "r"((uint32_t)(sa)), "r"((uint32_t)(n)) : "memory")
#define TCGEN05_DEALLOC(t, n) \
    asm volatile("tcgen05.dealloc.cta_group::1.sync.aligned.b32 %0, %1;" :: "r"(t), "r"((uint32_t)(n)))
#define TCGEN05_RELINQ() \
    asm volatile("tcgen05.relinquish_alloc_permit.cta_group::1.sync.aligned;")
#define TCGEN05_COMMIT(mb) \
    asm volatile("tcgen05.commit.cta_group::1.mbarrier::arrive::one.shared::cluster.b64 [%0];" \
                 :: "r"((uint32_t)(mb)) : "memory")
#define TCGEN05_WAIT_LD() asm volatile("tcgen05.wait::ld.sync.aligned;" ::: "memory")
#define TCGEN05_WAIT_ST() asm volatile("tcgen05.wait::st.sync.aligned;" ::: "memory")
#define TCGEN05_FENCE_BEFORE() asm volatile("tcgen05.fence::before_thread_sync;" ::: "memory")
#define TCGEN05_FENCE_AFTER()  asm volatile("tcgen05.fence::after_thread_sync;" ::: "memory")
#define FENCE_PROXY_ASYNC() asm volatile("fence.proxy.async.shared::cta;" ::: "memory")

#define LDTM32(r, ta) \
    asm volatile( \
        "tcgen05.ld.sync.aligned.32x32b.x32.b32 " \
        "{%0, %1, %2, %3, %4, %5, %6, %7, " \
        " %8, %9, %10, %11, %12, %13, %14, %15, " \
        " %16, %17, %18, %19, %20, %21, %22, %23, " \
        " %24, %25, %26, %27, %28, %29, %30, %31}, [%32];" \
        : "=r"((r)[0]),  "=r"((r)[1]),  "=r"((r)[2]),  "=r"((r)[3]), \
          "=r"((r)[4]),  "=r"((r)[5]),  "=r"((r)[6]),  "=r"((r)[7]), \
          "=r"((r)[8]),  "=r"((r)[9]),  "=r"((r)[10]), "=r"((r)[11]), \
          "=r"((r)[12]), "=r"((r)[13]), "=r"((r)[14]), "=r"((r)[15]), \
          "=r"((r)[16]), "=r"((r)[17]), "=r"((r)[18]), "=r"((r)[19]), \
          "=r"((r)[20]), "=r"((r)[21]), "=r"((r)[22]), "=r"((r)[23]), \
          "=r"((r)[24]), "=r"((r)[25]), "=r"((r)[26]), "=r"((r)[27]), \
          "=r"((r)[28]), "=r"((r)[29]), "=r"((r)[30]), "=r"((r)[31]) \
        : "r"(ta))

#define STTM16(ta, r) \
    asm volatile( \
        "tcgen05.st.sync.aligned.32x32b.x16.b32 [%0], " \
        "{%1, %2, %3, %4, %5, %6, %7, %8, " \
        " %9, %10, %11, %12, %13, %14, %15, %16};" \
        :: "r"(ta), \
           "r"((r)[0]),  "r"((r)[1]),  "r"((r)[2]),  "r"((r)[3]), \
           "r"((r)[4]),  "r"((r)[5]),  "r"((r)[6]),  "r"((r)[7]), \
           "r"((r)[8]),  "r"((r)[9]),  "r"((r)[10]), "r"((r)[11]), \
           "r"((r)[12]), "r"((r)[13]), "r"((r)[14]), "r"((r)[15]) \
        : "memory")

static constexpr uint64_t DESC_BASE_SW128 =
    (uint64_t(2) << 61) | (uint64_t(1) << 46) | (uint64_t(64) << 32) | (uint64_t(1) << 16);
#define MAKE_DESC(addr) (DESC_BASE_SW128 | ((uint64_t)((addr) >> 4) & 0x3FFF))

__device__ __forceinline__ void mma_f16_ss(uint32_t d, uint64_t ad, uint64_t bd,
                                           uint32_t idesc, bool en) {
    uint32_t e = en ? 1u : 0u;
    asm volatile(
        "{\n\t.reg .pred p;\n\tsetp.ne.u32 p, %4, 0;\n\t"
        "tcgen05.mma.cta_group::1.kind::f16 [%0], %1, %2, %3, {%5, %5, %5, %5}, p;\n\t}"
        :: "r"(d), "l"(ad), "l"(bd), "r"(idesc), "r"(e), "r"(0u) : "memory");
}
__device__ __forceinline__ void mma_f16_ts(uint32_t d, uint32_t at, uint64_t bd,
                                           uint32_t idesc, bool en) {
    uint32_t e = en ? 1u : 0u;
    asm volatile(
        "{\n\t.reg .pred p;\n\tsetp.ne.u32 p, %4, 0;\n\t"
        "tcgen05.mma.cta_group::1.kind::f16 [%0], [%1], %2, %3, {%5, %5, %5, %5}, p;\n\t}"
        :: "r"(d), "r"(at), "l"(bd), "r"(idesc), "r"(e), "r"(0u) : "memory");
}
#endif  // AE_TC

// ---------------------------------------------------------------------------
// SMEM layout (bytes)
// ---------------------------------------------------------------------------
#define SM_S1A     0           // stage1 A bufs: 2 x 32KB (2 levels x 16KB)
#define SM_S1B     65536       // stage1 B bufs: 2 x 64KB (2 levels x 32KB, 256 rows)
#define SM_S2B     65536       // stage2 B bufs: 4 x 32KB (overlays S1B region)
#define SM_B1S     196608      // b1 copy (1 KB)
#define SM_B2S     197632      // b2 copy (4 KB)
#define SM_FULL(i) (201728 + (i) * 8)   // 4 full bars (producer -> issuer)
#define SM_SD1(i)  (201760 + (i) * 8)   // 2 stage-1 slot-done bars
#define SM_SD2(i)  (201776 + (i) * 8)   // 8 stage-2 slot-done bars
#define SM_ED(i)   (201840 + (i) * 8)   // 2 epilogue-done bars
#define SM_TMEMPTR 201856
#define SMEM_TOTAL 201984

// TMEM column layout (512 cols)
#define TM_D1   0      // stage1 accum h [128 x 256] f32 (dead after epi1)
#define TM_D2   0      // stage2 ping-pong accum [128 x 64] f32 x 2 — in dead D1
#define TM_A0   256    // h split level0 (fp16x2, 128 cols)
#define TM_A1   384    // h split level1

// idesc: dtype F32 (bit4) | atype/btype F16=0 | N/8<<17 | M/16<<24
#define IDESC_N256 ((8u << 24) | (32u << 17) | (1u << 4))
#define IDESC_N64  ((8u << 24) | (8u  << 17) | (1u << 4))

// ---------------------------------------------------------------------------
// Fused prep kernel: split_x (float4-vectorized) + tr_w1 + tr_w2, one launch.
// ---------------------------------------------------------------------------
#define PREP_SPLITX_BLOCKS (BX * DX / 4 / 256)              // 8192
#define PREP_W1_BLOCKS     ((HX / 32) * (DX / 32) * KX)     // 2048
#define PREP_W2_BLOCKS     ((DX / 32) * (HX / 32) * KX)     // 2048
#define PREP_TOTAL_BLOCKS  (PREP_SPLITX_BLOCKS + PREP_W1_BLOCKS + PREP_W2_BLOCKS)

__global__ __launch_bounds__(256)
void prep_kernel(const float* __restrict__ x,
                 const float* __restrict__ W1,
                 const float* __restrict__ W2)
{
    __shared__ float t[32][33];
    const int blk = blockIdx.x;
    const int tid = threadIdx.x;

    if (blk < PREP_SPLITX_BLOCKS) {
        // ---- split_x: 4 elems/thread; word j of each level covers elems 2j,2j+1
        size_t i4 = (size_t)blk * 256 + tid;           // quad index
        float4 v = ((const float4*)x)[i4];
        __half a0, a1, b0, b1, c0, c1, d0, d1;
        split2(v.x, a0, a1);
        split2(v.y, b0, b1);
        split2(v.z, c0, c1);
        split2(v.w, d0, d1);
        const size_t NW = (size_t)BX * DX / 2;         // words per level
        uint2 w0 = make_uint2(pack2h(a0, b0), pack2h(c0, d0));
        uint2 w1 = make_uint2(pack2h(a1, b1), pack2h(c1, d1));
        ((uint2*)g_xs)[i4]            = w0;            // level 0, words 2i4, 2i4+1
        ((uint2*)((uint32_t*)g_xs + NW))[i4] = w1;     // level 1
        return;
    }

    const int tx = tid & 31, ty = tid >> 5;     // (32, 8) thread shape

    if (blk < PREP_SPLITX_BLOCKS + PREP_W1_BLOCKS) {
        // ---- tr_w1: idx -> (h0, d0, k) ----
        int idx = blk - PREP_SPLITX_BLOCKS;
        int h0 = (idx % (HX / 32)) * 32;
        int d0 = ((idx / (HX / 32)) % (DX / 32)) * 32;
        int k  = idx / ((HX / 32) * (DX / 32));
        #pragma unroll
        for (int r = 0; r < 4; r++) {
            int d = d0 + ty + r * 8;
            t[ty + r * 8][tx] = W1[((size_t)k * DX + d) * HX + h0 + tx];
        }
        __syncthreads();
        const size_t LVL = (size_t)KX * HX * DX;
        #pragma unroll
        for (int r = 0; r < 4; r++) {
            int h = h0 + ty + r * 8;
            float v = t[tx][ty + r * 8];
            __half a0, a1;
            split2(v, a0, a1);
            size_t base = ((size_t)k * HX + h) * DX + d0 + tx;
            g_w1t[base] = a0; g_w1t[LVL + base] = a1;
        }
        return;
    }

    {
        // ---- tr_w2: idx -> (d0, h0, k) ----
        int idx = blk - PREP_SPLITX_BLOCKS - PREP_W1_BLOCKS;
        int d0 = (idx % (DX / 32)) * 32;
        int h0 = ((idx / (DX / 32)) % (HX / 32)) * 32;
        int k  = idx / ((DX / 32) * (HX / 32));
        #pragma unroll
        for (int r = 0; r < 4; r++) {
            int h = h0 + ty + r * 8;
            t[ty + r * 8][tx] = W2[((size_t)k * HX + h) * DX + d0 + tx];
        }
        __syncthreads();
        const size_t LVL = (size_t)KX * DX * HX;
        #pragma unroll
        for (int r = 0; r < 4; r++) {
            int d = d0 + ty + r * 8;
            float v = t[tx][ty + r * 8];
            __half a0, a1;
            split2(v, a0, a1);
            size_t base = ((size_t)k * DX + d) * HX + h0 + tx;
            g_w2t[base] = a0; g_w2t[LVL + base] = a1;
        }
    }
}

#if AE_TC
// ---------------------------------------------------------------------------
// Producer tile loaders (96 threads: ptid = tid - 128, stride 96)
// ---------------------------------------------------------------------------
__device__ __forceinline__ void load_s1A(uint32_t sb, int buf, int kc, int b0, int ptid) {
    uint32_t base = sb + SM_S1A + buf * 32768;
    for (int t = ptid; t < 2048; t += 96) {       // 2 levels x [128 rows x 64] fp16
        int l = t >> 10, rem = t & 1023, r = rem >> 3, c = rem & 7;
        uint32_t dst = base + l * 16384 + SW128((uint32_t)(r * 128 + c * 16));
        const __half* src = g_xs + ((size_t)l * BX + b0 + r) * DX + kc * 64 + c * 8;
        CP16(dst, src);
    }
}
__device__ __forceinline__ void load_s1B(uint32_t sb, int buf, int kc, int k, int ptid) {
    uint32_t base = sb + SM_S1B + buf * 65536;
    for (int t = ptid; t < 4096; t += 96) {       // 2 levels x [256 h-rows x 64] fp16
        int l = t >> 11, rem = t & 2047, r = rem >> 3, c = rem & 7;
        uint32_t dst = base + l * 32768 + SW128((uint32_t)(r * 128 + c * 16));
        const __half* src =
            g_w1t + (((size_t)l * KX + k) * HX + r) * DX + kc * 64 + c * 8;
        CP16(dst, src);
    }
}
// stage-2 tile: 2 levels x 2 ks-sub (K=64 each) x [64 d-rows x 64] = 32 KB
__device__ __forceinline__ void load_s2B(uint32_t sb, int buf, int nc, int kh, int k,
                                         int ptid) {
    uint32_t base = sb + SM_S2B + buf * 32768;
    for (int t = ptid; t < 2048; t += 96) {
        int l = t >> 10, rem = t & 1023, ks = rem >> 9, rem2 = rem & 511;
        int r = rem2 >> 3, c = rem2 & 7;
        uint32_t dst = base + l * 16384 + ks * 8192 + SW128((uint32_t)(r * 128 + c * 16));
        const __half* src =
            g_w2t + (((size_t)l * KX + k) * DX + nc * 64 + r) * HX + kh * 128 + ks * 64 + c * 8;
        CP16(dst, src);
    }
}
#endif

// ---------------------------------------------------------------------------
// Main fused kernel: warp-specialized, 48 fat slots, deep look-ahead (R11).
//   warps 0-3: epilogues,  warps 4-6: producers,  warp 7 lane 0: MMA issuer
// ---------------------------------------------------------------------------
__global__ __launch_bounds__(256, 1)
void ae_main(const float* __restrict__ x,
             const float* __restrict__ b1,
             const float* __restrict__ b2)
{
#if AE_TC
    extern __shared__ char smem[];
    const uint32_t sb = smem_u32(smem);
    const int tid = threadIdx.x, wid = tid >> 5, lane = tid & 31;
    const int k = blockIdx.y, b0 = blockIdx.x * BM;

    if (wid == 0) TCGEN05_ALLOC(sb + SM_TMEMPTR, 512);
    if (tid == 0) {
        #pragma unroll
        for (int i = 0; i < 4; i++) MBARRIER_INIT(SM_FULL(i) + sb, 96);
        #pragma unroll
        for (int i = 0; i < 2; i++) MBARRIER_INIT(SM_SD1(i) + sb, 1);
        #pragma unroll
        for (int i = 0; i < 8; i++) MBARRIER_INIT(SM_SD2(i) + sb, 1);
        #pragma unroll
        for (int i = 0; i < 2; i++) MBARRIER_INIT(SM_ED(i) + sb, 128);
    }
    if (tid < 64) {
        float4 v = ((const float4*)(b1 + (size_t)k * HX))[tid];
        ((float4*)(smem + SM_B1S))[tid] = v;
    }
    {
        float4 v = ((const float4*)(b2 + (size_t)k * DX))[tid];
        ((float4*)(smem + SM_B2S))[tid] = v;
    }
    __syncthreads();
    uint32_t tb;
    asm volatile("ld.shared.b32 %0, [%1];" : "=r"(tb) : "r"(sb + SM_TMEMPTR));

    // 3 cross-products of the 2-level splits: (A0,B0), (A1,B0), (A0,B1)
    const int pa[3] = {0, 1, 0};
    const int pb[3] = {0, 0, 1};

    if (tid >= 128 && tid < 224) {
        // ===================== PRODUCERS (warps 4-6) ========================
        const int ptid = tid - 128;
        // stage 1: 16 slots (s == kc), A and B double-buffered on s&1.
        for (int s = 0; s < 16; s++) {
            if (s >= 2)
                MBARRIER_WAIT_PARITY(sb + SM_SD1(s & 1), ((s - 2) >> 1) & 1);
            load_s1A(sb, s & 1, s, b0, ptid);
            load_s1B(sb, s & 1, s, k, ptid);
            CP_ASYNC_ARRIVE(sb + SM_FULL(s & 3));
        }
        // stage 2: 32 slots (t = 2*nc + kh), bufs t&3 (32KB over the S1B region).
        // Bufs 0,1 overlay S1B buf0 (freed by MMA slot 14 = SD1(0)#8, parity 1);
        // bufs 2,3 overlay S1B buf1 (freed by MMA slot 15 = SD1(1)#8, parity 1).
        for (int t = 0; t < 32; t++) {
            if (t < 2)       MBARRIER_WAIT_PARITY(sb + SM_SD1(0), 1);
            else if (t < 4)  MBARRIER_WAIT_PARITY(sb + SM_SD1(1), 1);
            else             MBARRIER_WAIT_PARITY(sb + SM_SD2((t - 4) & 7), ((t - 4) >> 3) & 1);
            load_s2B(sb, t & 3, t >> 1, t & 1, k, ptid);
            CP_ASYNC_ARRIVE(sb + SM_FULL(t & 3));
        }
    } else if (tid == 224) {
        // ===================== MMA ISSUER (warp 7, lane 0) ==================
        // stage 1: 16 slots, N=256 atoms, 12 dispatches/slot
        for (int s = 0; s < 16; s++) {
            MBARRIER_WAIT_PARITY(sb + SM_FULL(s & 3), (s >> 2) & 1);
            FENCE_PROXY_ASYNC();
            uint32_t abuf = sb + SM_S1A + (s & 1) * 32768;
            uint32_t bbuf = sb + SM_S1B + (s & 1) * 65536;
            #pragma unroll
            for (int p = 0; p < 3; p++) {
                uint64_t ad = MAKE_DESC(abuf + pa[p] * 16384);
                uint64_t bd = MAKE_DESC(bbuf + pb[p] * 32768);
                #pragma unroll
                for (int st = 0; st < 4; st++) {
                    bool en = !(s == 0 && p == 0 && st == 0);
                    mma_f16_ss(tb + TM_D1, ad + st * 2, bd + st * 2, IDESC_N256, en);
                }
            }
            TCGEN05_COMMIT(sb + SM_SD1(s & 1));
        }
        // stage 2: 32 slots, 24 dispatches/slot
        MBARRIER_WAIT_PARITY(sb + SM_ED(0), 0);          // epilogue-1 done (A in TMEM)
        TCGEN05_FENCE_AFTER();
        const uint32_t abase[2] = {TM_A0, TM_A1};
        for (int t = 0; t < 32; t++) {
            const int nc = t >> 1, kh = t & 1;
            if (kh == 0 && nc >= 2) {                    // D2 ping-pong guard
                if (nc & 1) MBARRIER_WAIT_PARITY(sb + SM_ED(1), ((nc - 3) >> 1) & 1);
                else        MBARRIER_WAIT_PARITY(sb + SM_ED(0), (nc >> 1) & 1);
                TCGEN05_FENCE_AFTER();
            }
            // FULL(t&3): stage-1 consumed 4 phases; next parity = (t>>2)&1
            MBARRIER_WAIT_PARITY(sb + SM_FULL(t & 3), (t >> 2) & 1);
            FENCE_PROXY_ASYNC();
            uint32_t bbuf = sb + SM_S2B + (t & 3) * 32768;
            uint32_t d = tb + TM_D2 + (nc & 1) * 64;
            #pragma unroll
            for (int ks = 0; ks < 2; ks++) {
                #pragma unroll
                for (int p = 0; p < 3; p++) {
                    uint64_t bd = MAKE_DESC(bbuf + pb[p] * 16384 + ks * 8192);
                    #pragma unroll
                    for (int st = 0; st < 4; st++) {
                        bool en = !(kh == 0 && ks == 0 && p == 0 && st == 0);
                        uint32_t at = tb + abase[pa[p]] + (kh * 8 + ks * 4 + st) * 8;
                        mma_f16_ts(d, at, bd + st * 2, IDESC_N64, en);
                    }
                }
            }
            TCGEN05_COMMIT(sb + SM_SD2(t & 7));
        }
    } else if (tid < 128) {
        // ===================== EPILOGUE CREW (warps 0-3) ====================
        // wait all 8 completions of SD1(1) sequentially (slot 15 = 8th commit)
        for (int u = 0; u < 8; u++)
            MBARRIER_WAIT_PARITY(sb + SM_SD1(1), u & 1);
        TCGEN05_FENCE_AFTER();

        // epilogue 1: bias+relu, split h -> fp16x2 into TMEM.
        {
            const uint32_t woff = (uint32_t)wid << 21;
            const float* b1s = (const float*)(smem + SM_B1S);
            for (int c0 = 0; c0 < 256; c0 += 32) {
                uint32_t r[32];
                LDTM32(r, tb + TM_D1 + c0);
                TCGEN05_WAIT_LD();
                uint32_t p0[16], p1[16];
                #pragma unroll
                for (int t2 = 0; t2 < 16; t2++) {
                    float v0 = __uint_as_float(r[2 * t2])     + b1s[c0 + 2 * t2];
                    float v1 = __uint_as_float(r[2 * t2 + 1]) + b1s[c0 + 2 * t2 + 1];
                    v0 = fmaxf(v0, 0.0f); v1 = fmaxf(v1, 0.0f);
                    __half a0, a1, c0h, c1h;
                    split2(v0, a0, a1);
                    split2(v1, c0h, c1h);
                    p0[t2] = pack2h(a0, c0h);
                    p1[t2] = pack2h(a1, c1h);
                }
                STTM16(tb + TM_A0 + (c0 >> 1) + woff, p0);
                STTM16(tb + TM_A1 + (c0 >> 1) + woff, p1);
                TCGEN05_WAIT_ST();
            }
            TCGEN05_FENCE_BEFORE();
        }
        MBARRIER_ARRIVE(sb + SM_ED(0));   // ED(0) completion #1

        // epilogue 2: per-nc bias + err + recon store.
        // nc done at commit(t=2nc+1) -> SD2((2nc+1)&7) parity ((2nc+1)>>3)&1.
        float errsum = 0.0f;
        const float* b2s = (const float*)(smem + SM_B2S);
        const int row = wid * 32 + lane, gr = b0 + row;
        for (int nc = 0; nc < 16; nc++) {
            MBARRIER_WAIT_PARITY(sb + SM_SD2((2 * nc + 1) & 7), ((2 * nc + 1) >> 3) & 1);
            TCGEN05_FENCE_AFTER();
            uint32_t r0[32], r1[32];
            LDTM32(r0, tb + TM_D2 + (nc & 1) * 64);
            LDTM32(r1, tb + TM_D2 + (nc & 1) * 64 + 32);
            TCGEN05_WAIT_LD();
            const float* xr = x + (size_t)gr * DX + nc * 64;
            float* rr = g_recon + ((size_t)k * BX + gr) * DX + nc * 64;
            #pragma unroll
            for (int q = 0; q < 16; q++) {
                int c = q * 4;
                const uint32_t* rv = (c < 32) ? (r0 + c) : (r1 + c - 32);
                float4 xv = *(const float4*)(xr + c);
                float4 ov;
                ov.x = __uint_as_float(rv[0]) + b2s[nc * 64 + c + 0];
                ov.y = __uint_as_float(rv[1]) + b2s[nc * 64 + c + 1];
                ov.z = __uint_as_float(rv[2]) + b2s[nc * 64 + c + 2];
                ov.w = __uint_as_float(rv[3]) + b2s[nc * 64 + c + 3];
                *(float4*)(rr + c) = ov;
                float d0 = ov.x - xv.x, d1 = ov.y - xv.y;
                float d2 = ov.z - xv.z, d3 = ov.w - xv.w;
                errsum = fmaf(d0, d0, errsum);
                errsum = fmaf(d1, d1, errsum);
                errsum = fmaf(d2, d2, errsum);
                errsum = fmaf(d3, d3, errsum);
            }
            TCGEN05_FENCE_BEFORE();
            MBARRIER_ARRIVE(sb + SM_ED(nc & 1));
        }
        g_err[(size_t)k * BX + b0 + row] = errsum * (1.0f / DX);
    }
    // (tid 225..255: idle straight to the final barrier)

    __syncthreads();
    if (tid == 0) {
        #pragma unroll
        for (int i = 0; i < 4; i++) MBARRIER_INVAL(SM_FULL(i) + sb);
        #pragma unroll
        for (int i = 0; i < 2; i++) MBARRIER_INVAL(SM_SD1(i) + sb);
        #pragma unroll
        for (int i = 0; i < 8; i++) MBARRIER_INVAL(SM_SD2(i) + sb);
        #pragma unroll
        for (int i = 0; i < 2; i++) MBARRIER_INVAL(SM_ED(i) + sb);
    }
    __syncthreads();
    if (wid == 0) {
        TCGEN05_RELINQ();
        TCGEN05_DEALLOC(tb, 512);
    }
#else
    // ---------------- Correct scalar fallback (non-arch-specific pass) -------
    extern __shared__ char smem[];
    float* h_f = (float*)smem;                     // [128][256]
    float* errsh = h_f + BM * HX;                  // [128]
    const int tid = threadIdx.x;
    const int k = blockIdx.y, b0 = blockIdx.x * BM;
    const size_t L1 = (size_t)KX * HX * DX;
    const size_t L2 = (size_t)KX * DX * HX;

    for (int i = tid; i < BM * HX; i += 256) {
        int r = i >> 8, c = i & 255;
        float s = b1[(size_t)k * HX + c];
        const float* xr = x + (size_t)(b0 + r) * DX;
        size_t wb = ((size_t)k * HX + c) * DX;
        for (int d = 0; d < DX; d++) {
            float w = __half2float(g_w1t[wb + d]) + __half2float(g_w1t[L1 + wb + d]);
            s = fmaf(xr[d], w, s);
        }
        h_f[i] = fmaxf(s, 0.0f);
    }
    __syncthreads();
    if (tid < 128) errsh[tid] = 0.0f;
    __syncthreads();
    for (int i = tid; i < BM * DX; i += 256) {
        int r = i >> 10, c = i & 1023;
        float s = b2[(size_t)k * DX + c];
        size_t wb = ((size_t)k * DX + c) * HX;
        for (int hh = 0; hh < HX; hh++) {
            float w = __half2float(g_w2t[wb + hh]) + __half2float(g_w2t[L2 + wb + hh]);
            s = fmaf(h_f[r * HX + hh], w, s);
        }
        g_recon[((size_t)k * BX + b0 + r) * DX + c] = s;
        float d = s - x[(size_t)(b0 + r) * DX + c];
        atomicAdd(&errsh[r], d * d);
    }
    __syncthreads();
    if (tid < 128) g_err[(size_t)k * BX + b0 + tid] = errsh[tid] * (1.0f / DX);
#endif
}

// ---------------------------------------------------------------------------
// Argmin + gather
// ---------------------------------------------------------------------------
__global__ __launch_bounds__(256)
void ae_assign_gather_kernel(float* __restrict__ out)
{
    const int warp = threadIdx.x >> 5;
    const int lane = threadIdx.x & 31;
    const int b = blockIdx.x * 8 + warp;
    if (b >= BX) return;

    float best = g_err[b];
    int bi = 0;
    #pragma unroll
    for (int kk = 1; kk < KX; kk++) {
        float e = g_err[(size_t)kk * BX + b];
        if (e < best) { best = e; bi = kk; }
    }
    const float4* src = (const float4*)(g_recon + ((size_t)bi * BX + b) * DX);
    float4* dst = (float4*)(out + (size_t)b * DX);
    #pragma unroll
    for (int j = 0; j < 8; j++)
        dst[lane + 32 * j] = src[lane + 32 * j];
}

// ---------------------------------------------------------------------------
// Host launcher
// ---------------------------------------------------------------------------
extern "C" void kernel_launch(void* const* d_in, const int* in_sizes, int n_in,
                              void* d_out, int out_size)
{
    const float* x  = (const float*)d_in[0];
    const float* W1 = (const float*)d_in[1];
    const float* b1 = (const float*)d_in[2];
    const float* W2 = (const float*)d_in[3];
    const float* b2 = (const float*)d_in[4];
    float* out = (float*)d_out;

    prep_kernel<<<PREP_TOTAL_BLOCKS, 256>>>(x, W1, W2);

    cudaFuncSetAttribute(ae_main, cudaFuncAttributeMaxDynamicSharedMemorySize, SMEM_TOTAL);
    ae_main<<<dim3(BX / BM, KX), 256, SMEM_TOTAL>>>(x, b1, b2);

    ae_assign_gather_kernel<<<BX / 8, 256>>>(out);
}